// round 13
// baseline (speedup 1.0000x reference)
#include <cuda_runtime.h>
#include <math.h>

// AdaFace logit adjustment, two-phase (split WITHOUT the R5 reg cap):
//  1) stats_kernel: 1 block, 1024 threads, ~8KB traffic, no matrix access.
//     Computes norm mean / ddof-1 std and per-row (g_ang, g_add, target flat
//     index) into __device__ globals. ~2-3us.
//  2) stream_kernel: R12's proven hot loop (3552 blocks = 4 waves of dynamic
//     backfill, natural 40-reg codegen, 4-deep float4 MLP batch, .cs hints),
//     with the per-block stats prologue replaced by a ~3-load target scan.
//   out = logits * 64, except out[r, labels[r]] =
//         (cos(clip(acos(t)+g_ang, eps, pi-eps)) - g_add) * 64

#define B_ROWS   1024
#define SCALE    64.0f
#define MARGIN   0.4f
#define H_CONST  0.333f
#define EPS_CONST 1e-3f
#define THREADS  256
#define NBLOCKS  (148 * 24)
#define MAXT     4

__device__ float d_ga[B_ROWS];   // per-row angular margin
__device__ float d_gd[B_ROWS];   // per-row additive cosine margin
__device__ int   d_tgt[B_ROWS];  // per-row target flat element index

// ---------------------------------------------------------------------------
// Phase 1: stats + per-row margin params. 1 block, 1024 threads.
// ---------------------------------------------------------------------------
__global__ void __launch_bounds__(B_ROWS)
stats_kernel(const float* __restrict__ norms,
             const int*   __restrict__ labels,
             int C) {
    __shared__ float red[32];
    const int tid = threadIdx.x;

    float x = norms[tid];
    x = fminf(fmaxf(x, 1e-3f), 100.0f);

    // block sum -> mean
    float v = x;
    #pragma unroll
    for (int o = 16; o > 0; o >>= 1) v += __shfl_down_sync(0xffffffffu, v, o);
    int lane = tid & 31, warp = tid >> 5;
    if (lane == 0) red[warp] = v;
    __syncthreads();
    if (warp == 0) {
        v = red[lane];
        #pragma unroll
        for (int o = 16; o > 0; o >>= 1) v += __shfl_down_sync(0xffffffffu, v, o);
        if (lane == 0) red[0] = v;
    }
    __syncthreads();
    float mean = red[0] * (1.0f / B_ROWS);
    __syncthreads();

    // block sum of squared deviations -> unbiased std (ddof = 1)
    float dv = x - mean;
    v = dv * dv;
    #pragma unroll
    for (int o = 16; o > 0; o >>= 1) v += __shfl_down_sync(0xffffffffu, v, o);
    if (lane == 0) red[warp] = v;
    __syncthreads();
    if (warp == 0) {
        v = red[lane];
        #pragma unroll
        for (int o = 16; o > 0; o >>= 1) v += __shfl_down_sync(0xffffffffu, v, o);
        if (lane == 0) red[0] = v;
    }
    __syncthreads();
    float stdv = sqrtf(red[0] * (1.0f / (B_ROWS - 1)));

    float ms = (x - mean) * (H_CONST / (stdv + EPS_CONST));
    ms = fminf(fmaxf(ms, -1.0f), 1.0f);

    d_ga[tid]  = -MARGIN * ms;
    d_gd[tid]  = MARGIN + MARGIN * ms;
    d_tgt[tid] = tid * C + labels[tid];   // < 102.4M, fits int
}

// ---------------------------------------------------------------------------
// Phase 2: streaming scale + inline patch. Natural codegen (no reg cap).
// ---------------------------------------------------------------------------
__global__ void __launch_bounds__(THREADS)
stream_kernel(const float4* __restrict__ in,
              float4* __restrict__ out,
              int C, int n4) {
    __shared__ int   s_ntgt;
    __shared__ int   s_tgt_i4[MAXT];
    __shared__ int   s_tgt_c[MAXT];
    __shared__ float s_ga[MAXT];
    __shared__ float s_gd[MAXT];

    const int tid = threadIdx.x;

    // ---- block-contiguous chunk (~115KB, spans <= 2 rows) ----
    int chunk4 = (n4 + gridDim.x - 1) / gridDim.x;
    int i40 = blockIdx.x * chunk4;
    if (i40 >= n4) return;
    int i41 = min(n4, i40 + chunk4);

    // ---- target scan: <= 2 precomputed rows ----
    if (tid == 0) s_ntgt = 0;
    __syncthreads();
    {
        int e0 = i40 * 4;
        int e1 = i41 * 4;                 // exclusive; fits int (<= 102.4M)
        int r0 = e0 / C;
        int r1 = (e1 - 1) / C;
        int nrows = r1 - r0 + 1;          // 1..2
        if (tid < nrows && tid < MAXT) {
            int r = r0 + tid;
            int tgt = d_tgt[r];
            if (tgt >= e0 && tgt < e1) {
                int slot = atomicAdd(&s_ntgt, 1);
                s_tgt_i4[slot] = tgt >> 2;
                s_tgt_c[slot]  = tgt & 3;
                s_ga[slot]     = d_ga[r];
                s_gd[slot]     = d_gd[r];
            }
        }
    }
    __syncthreads();
    const int ntgt = s_ntgt;

    // ---- stream the chunk ----
    auto patch = [&](float4& v, int i4) {
        for (int t = 0; t < ntgt; t++) {
            if (i4 == s_tgt_i4[t]) {
                int c = s_tgt_c[t];
                float tv = (c == 0) ? v.x : (c == 1) ? v.y : (c == 2) ? v.z : v.w;
                float theta = acosf(tv) + s_ga[t];
                theta = fminf(fmaxf(theta, EPS_CONST), (float)M_PI - EPS_CONST);
                float nt = cosf(theta) - s_gd[t];
                switch (c) {
                    case 0: v.x = nt; break;
                    case 1: v.y = nt; break;
                    case 2: v.z = nt; break;
                    default: v.w = nt; break;
                }
            }
        }
    };

    int i = i40 + tid;
    for (; i + 3 * THREADS < i41; i += 4 * THREADS) {
        float4 v0 = __ldcs(&in[i]);
        float4 v1 = __ldcs(&in[i + THREADS]);
        float4 v2 = __ldcs(&in[i + 2 * THREADS]);
        float4 v3 = __ldcs(&in[i + 3 * THREADS]);
        if (ntgt) {
            patch(v0, i);
            patch(v1, i + THREADS);
            patch(v2, i + 2 * THREADS);
            patch(v3, i + 3 * THREADS);
        }
        v0.x *= SCALE; v0.y *= SCALE; v0.z *= SCALE; v0.w *= SCALE;
        v1.x *= SCALE; v1.y *= SCALE; v1.z *= SCALE; v1.w *= SCALE;
        v2.x *= SCALE; v2.y *= SCALE; v2.z *= SCALE; v2.w *= SCALE;
        v3.x *= SCALE; v3.y *= SCALE; v3.z *= SCALE; v3.w *= SCALE;
        __stcs(&out[i],               v0);
        __stcs(&out[i + THREADS],     v1);
        __stcs(&out[i + 2 * THREADS], v2);
        __stcs(&out[i + 3 * THREADS], v3);
    }
    for (; i < i41; i += THREADS) {
        float4 v = __ldcs(&in[i]);
        if (ntgt) patch(v, i);
        v.x *= SCALE; v.y *= SCALE; v.z *= SCALE; v.w *= SCALE;
        __stcs(&out[i], v);
    }
}

// ---------------------------------------------------------------------------
extern "C" void kernel_launch(void* const* d_in, const int* in_sizes, int n_in,
                              void* d_out, int out_size) {
    const float* logits = (const float*)d_in[0];
    const float* norms  = (const float*)d_in[1];
    const int*   labels = (const int*)d_in[2];
    float* out = (float*)d_out;

    int total = out_size;            // B*C = 102,400,000
    int C = total / B_ROWS;          // 100000
    int n4 = total / 4;              // 25,600,000 (C % 4 == 0)

    stats_kernel<<<1, B_ROWS>>>(norms, labels, C);
    stream_kernel<<<NBLOCKS, THREADS>>>((const float4*)logits, (float4*)out, C, n4);
}

// round 15
// speedup vs baseline: 1.0143x; 1.0143x over previous
#include <cuda_runtime.h>
#include <math.h>

// AdaFace logit adjustment, fused single streaming kernel with CONDITIONAL
// stats prologue.
//   out = logits * 64, except out[r, labels[r]] =
//         (cos(clip(acos(t)+g_ang, eps, pi-eps)) - g_add) * 64
// B=1024, C=100000, fp32. 800 MB HBM round trip.
//
// Whether a block needs the norm statistics is decidable from labels alone:
// target index = r*C + labels[r]. Each ~115KB chunk spans <=2 rows and only
// 1024/3552 chunks contain a target, so ~71% of blocks skip the stats
// reduction entirely (2 label loads + 1 barrier) and stream immediately.
// Grid = 3552 (4 waves): HW scheduler backfill absorbs per-CTA spread (R11/R12
// established multi-wave > one-wave). Natural 40-reg codegen keeps the 4-deep
// float4 load batch (R5 established reg caps kill MLP).

#define B_ROWS   1024
#define SCALE    64.0f
#define MARGIN   0.4f
#define H_CONST  0.333f
#define EPS_CONST 1e-3f
#define THREADS  256
#define NBLOCKS  (148 * 24)
#define MAXT     4

__device__ __forceinline__ float block_sum_256(float v, float* red) {
    #pragma unroll
    for (int o = 16; o > 0; o >>= 1)
        v += __shfl_down_sync(0xffffffffu, v, o);
    int lane = threadIdx.x & 31;
    int warp = threadIdx.x >> 5;
    if (lane == 0) red[warp] = v;
    __syncthreads();
    if (warp == 0) {
        v = (lane < THREADS / 32) ? red[lane] : 0.0f;
        #pragma unroll
        for (int o = 4; o > 0; o >>= 1)
            v += __shfl_down_sync(0xffffffffu, v, o);
        if (lane == 0) red[0] = v;
    }
    __syncthreads();
    float r = red[0];
    __syncthreads();
    return r;
}

__global__ void __launch_bounds__(THREADS)
fused_kernel(const float4* __restrict__ in,
             float4* __restrict__ out,
             const float* __restrict__ norms,
             const int*   __restrict__ labels,
             int C, int n4) {
    __shared__ float red[THREADS / 32];
    __shared__ int   s_ntgt;
    __shared__ int   s_tgt[MAXT];      // flat element index
    __shared__ int   s_row[MAXT];      // owning row
    __shared__ float s_ga[MAXT];
    __shared__ float s_gd[MAXT];

    const int tid = threadIdx.x;

    // ---- block-contiguous chunk (~115KB, spans <= 2 rows) ----
    int chunk4 = (n4 + gridDim.x - 1) / gridDim.x;
    int i40 = blockIdx.x * chunk4;
    if (i40 >= n4) return;
    int i41 = min(n4, i40 + chunk4);

    // ---- cheap target test: labels only, no stats ----
    if (tid == 0) s_ntgt = 0;
    __syncthreads();
    int e0 = i40 * 4;
    int e1 = i41 * 4;                  // exclusive; fits int (<= 102.4M)
    int r0 = e0 / C;
    int r1 = (e1 - 1) / C;
    int nrows = r1 - r0 + 1;           // 1..2
    if (tid < nrows && tid < MAXT) {
        int r = r0 + tid;
        int tgt = r * C + __ldg(&labels[r]);   // < 102.4M, fits int
        if (tgt >= e0 && tgt < e1) {
            int slot = atomicAdd(&s_ntgt, 1);
            s_tgt[slot] = tgt;
            s_row[slot] = r;
        }
    }
    __syncthreads();
    const int ntgt = s_ntgt;           // block-uniform

    // ---- stats prologue: ONLY if this block owns a target (~29% of blocks) ----
    if (ntgt) {
        float xl[B_ROWS / THREADS];
        float acc = 0.0f;
        #pragma unroll
        for (int k = 0; k < B_ROWS / THREADS; k++) {
            float x = norms[tid + k * THREADS];
            x = fminf(fmaxf(x, 1e-3f), 100.0f);
            xl[k] = x;
            acc += x;
        }
        float mean = block_sum_256(acc, red) * (1.0f / B_ROWS);
        float vacc = 0.0f;
        #pragma unroll
        for (int k = 0; k < B_ROWS / THREADS; k++) {
            float d = xl[k] - mean;
            vacc += d * d;
        }
        float stdv = sqrtf(block_sum_256(vacc, red) * (1.0f / (B_ROWS - 1)));
        float inv_sh = H_CONST / (stdv + EPS_CONST);

        if (tid < ntgt) {
            int r = s_row[tid];
            float x = fminf(fmaxf(norms[r], 1e-3f), 100.0f);
            float ms = (x - mean) * inv_sh;
            ms = fminf(fmaxf(ms, -1.0f), 1.0f);
            s_ga[tid] = -MARGIN * ms;
            s_gd[tid] = MARGIN + MARGIN * ms;
        }
        __syncthreads();
    }

    // ---- stream the chunk ----
    auto patch = [&](float4& v, int i4) {
        for (int t = 0; t < ntgt; t++) {
            int tg = s_tgt[t];
            if (i4 == (tg >> 2)) {
                int c = tg & 3;
                float tv = (c == 0) ? v.x : (c == 1) ? v.y : (c == 2) ? v.z : v.w;
                float theta = acosf(tv) + s_ga[t];
                theta = fminf(fmaxf(theta, EPS_CONST), (float)M_PI - EPS_CONST);
                float nt = cosf(theta) - s_gd[t];
                switch (c) {
                    case 0: v.x = nt; break;
                    case 1: v.y = nt; break;
                    case 2: v.z = nt; break;
                    default: v.w = nt; break;
                }
            }
        }
    };

    int i = i40 + tid;
    for (; i + 3 * THREADS < i41; i += 4 * THREADS) {
        float4 v0 = __ldcs(&in[i]);
        float4 v1 = __ldcs(&in[i + THREADS]);
        float4 v2 = __ldcs(&in[i + 2 * THREADS]);
        float4 v3 = __ldcs(&in[i + 3 * THREADS]);
        if (ntgt) {
            patch(v0, i);
            patch(v1, i + THREADS);
            patch(v2, i + 2 * THREADS);
            patch(v3, i + 3 * THREADS);
        }
        v0.x *= SCALE; v0.y *= SCALE; v0.z *= SCALE; v0.w *= SCALE;
        v1.x *= SCALE; v1.y *= SCALE; v1.z *= SCALE; v1.w *= SCALE;
        v2.x *= SCALE; v2.y *= SCALE; v2.z *= SCALE; v2.w *= SCALE;
        v3.x *= SCALE; v3.y *= SCALE; v3.z *= SCALE; v3.w *= SCALE;
        __stcs(&out[i],               v0);
        __stcs(&out[i + THREADS],     v1);
        __stcs(&out[i + 2 * THREADS], v2);
        __stcs(&out[i + 3 * THREADS], v3);
    }
    for (; i < i41; i += THREADS) {
        float4 v = __ldcs(&in[i]);
        if (ntgt) patch(v, i);
        v.x *= SCALE; v.y *= SCALE; v.z *= SCALE; v.w *= SCALE;
        __stcs(&out[i], v);
    }
}

extern "C" void kernel_launch(void* const* d_in, const int* in_sizes, int n_in,
                              void* d_out, int out_size) {
    const float* logits = (const float*)d_in[0];
    const float* norms  = (const float*)d_in[1];
    const int*   labels = (const int*)d_in[2];
    float* out = (float*)d_out;

    int total = out_size;            // B*C = 102,400,000
    int C = total / B_ROWS;          // 100000
    int n4 = total / 4;              // 25,600,000 (C % 4 == 0)

    fused_kernel<<<NBLOCKS, THREADS>>>((const float4*)logits, (float4*)out,
                                       norms, labels, C, n4);
}

// round 16
// speedup vs baseline: 1.0364x; 1.0218x over previous
#include <cuda_runtime.h>
#include <math.h>

// AdaFace logit adjustment, fused single streaming kernel with CONDITIONAL
// stats prologue.
//   out = logits * 64, except out[r, labels[r]] =
//         (cos(clip(acos(t)+g_ang, eps, pi-eps)) - g_add) * 64
// B=1024, C=100000, fp32. 800 MB HBM round trip.
//
// Grid = 7104 (48/SM launched, 6 resident => 8 waves). Wave-count scaling has
// been monotone (1w:70.9% -> 1.33w:74.1% -> 4w:78.7% DRAM); finer chunks
// (~57KB) shrink the end-of-kernel imbalance window. Only ~14% of blocks
// contain a target row (decidable from labels alone), so the stats reduction
// is skipped by the rest (2 label loads + 1 barrier). Natural 40-reg codegen
// preserves the 4-deep float4 load batch (R5: reg caps kill MLP).

#define B_ROWS   1024
#define SCALE    64.0f
#define MARGIN   0.4f
#define H_CONST  0.333f
#define EPS_CONST 1e-3f
#define THREADS  256
#define NBLOCKS  (148 * 48)
#define MAXT     4

__device__ __forceinline__ float block_sum_256(float v, float* red) {
    #pragma unroll
    for (int o = 16; o > 0; o >>= 1)
        v += __shfl_down_sync(0xffffffffu, v, o);
    int lane = threadIdx.x & 31;
    int warp = threadIdx.x >> 5;
    if (lane == 0) red[warp] = v;
    __syncthreads();
    if (warp == 0) {
        v = (lane < THREADS / 32) ? red[lane] : 0.0f;
        #pragma unroll
        for (int o = 4; o > 0; o >>= 1)
            v += __shfl_down_sync(0xffffffffu, v, o);
        if (lane == 0) red[0] = v;
    }
    __syncthreads();
    float r = red[0];
    __syncthreads();
    return r;
}

__global__ void __launch_bounds__(THREADS)
fused_kernel(const float4* __restrict__ in,
             float4* __restrict__ out,
             const float* __restrict__ norms,
             const int*   __restrict__ labels,
             int C, int n4) {
    __shared__ float red[THREADS / 32];
    __shared__ int   s_ntgt;
    __shared__ int   s_tgt[MAXT];      // flat element index
    __shared__ int   s_row[MAXT];      // owning row
    __shared__ float s_ga[MAXT];
    __shared__ float s_gd[MAXT];

    const int tid = threadIdx.x;

    // ---- block-contiguous chunk (~57KB, spans <= 2 rows) ----
    int chunk4 = (n4 + gridDim.x - 1) / gridDim.x;
    int i40 = blockIdx.x * chunk4;
    if (i40 >= n4) return;
    int i41 = min(n4, i40 + chunk4);

    // ---- cheap target test: labels only, no stats ----
    if (tid == 0) s_ntgt = 0;
    __syncthreads();
    int e0 = i40 * 4;
    int e1 = i41 * 4;                  // exclusive; fits int (<= 102.4M)
    int r0 = e0 / C;
    int r1 = (e1 - 1) / C;
    int nrows = r1 - r0 + 1;           // 1..2
    if (tid < nrows && tid < MAXT) {
        int r = r0 + tid;
        int tgt = r * C + __ldg(&labels[r]);   // < 102.4M, fits int
        if (tgt >= e0 && tgt < e1) {
            int slot = atomicAdd(&s_ntgt, 1);
            s_tgt[slot] = tgt;
            s_row[slot] = r;
        }
    }
    __syncthreads();
    const int ntgt = s_ntgt;           // block-uniform

    // ---- stats prologue: ONLY if this block owns a target (~14% of blocks) ----
    if (ntgt) {
        float xl[B_ROWS / THREADS];
        float acc = 0.0f;
        #pragma unroll
        for (int k = 0; k < B_ROWS / THREADS; k++) {
            float x = norms[tid + k * THREADS];
            x = fminf(fmaxf(x, 1e-3f), 100.0f);
            xl[k] = x;
            acc += x;
        }
        float mean = block_sum_256(acc, red) * (1.0f / B_ROWS);
        float vacc = 0.0f;
        #pragma unroll
        for (int k = 0; k < B_ROWS / THREADS; k++) {
            float d = xl[k] - mean;
            vacc += d * d;
        }
        float stdv = sqrtf(block_sum_256(vacc, red) * (1.0f / (B_ROWS - 1)));
        float inv_sh = H_CONST / (stdv + EPS_CONST);

        if (tid < ntgt) {
            int r = s_row[tid];
            float x = fminf(fmaxf(norms[r], 1e-3f), 100.0f);
            float ms = (x - mean) * inv_sh;
            ms = fminf(fmaxf(ms, -1.0f), 1.0f);
            s_ga[tid] = -MARGIN * ms;
            s_gd[tid] = MARGIN + MARGIN * ms;
        }
        __syncthreads();
    }

    // ---- stream the chunk ----
    auto patch = [&](float4& v, int i4) {
        for (int t = 0; t < ntgt; t++) {
            int tg = s_tgt[t];
            if (i4 == (tg >> 2)) {
                int c = tg & 3;
                float tv = (c == 0) ? v.x : (c == 1) ? v.y : (c == 2) ? v.z : v.w;
                float theta = acosf(tv) + s_ga[t];
                theta = fminf(fmaxf(theta, EPS_CONST), (float)M_PI - EPS_CONST);
                float nt = cosf(theta) - s_gd[t];
                switch (c) {
                    case 0: v.x = nt; break;
                    case 1: v.y = nt; break;
                    case 2: v.z = nt; break;
                    default: v.w = nt; break;
                }
            }
        }
    };

    int i = i40 + tid;
    for (; i + 3 * THREADS < i41; i += 4 * THREADS) {
        float4 v0 = __ldcs(&in[i]);
        float4 v1 = __ldcs(&in[i + THREADS]);
        float4 v2 = __ldcs(&in[i + 2 * THREADS]);
        float4 v3 = __ldcs(&in[i + 3 * THREADS]);
        if (ntgt) {
            patch(v0, i);
            patch(v1, i + THREADS);
            patch(v2, i + 2 * THREADS);
            patch(v3, i + 3 * THREADS);
        }
        v0.x *= SCALE; v0.y *= SCALE; v0.z *= SCALE; v0.w *= SCALE;
        v1.x *= SCALE; v1.y *= SCALE; v1.z *= SCALE; v1.w *= SCALE;
        v2.x *= SCALE; v2.y *= SCALE; v2.z *= SCALE; v2.w *= SCALE;
        v3.x *= SCALE; v3.y *= SCALE; v3.z *= SCALE; v3.w *= SCALE;
        __stcs(&out[i],               v0);
        __stcs(&out[i + THREADS],     v1);
        __stcs(&out[i + 2 * THREADS], v2);
        __stcs(&out[i + 3 * THREADS], v3);
    }
    for (; i < i41; i += THREADS) {
        float4 v = __ldcs(&in[i]);
        if (ntgt) patch(v, i);
        v.x *= SCALE; v.y *= SCALE; v.z *= SCALE; v.w *= SCALE;
        __stcs(&out[i], v);
    }
}

extern "C" void kernel_launch(void* const* d_in, const int* in_sizes, int n_in,
                              void* d_out, int out_size) {
    const float* logits = (const float*)d_in[0];
    const float* norms  = (const float*)d_in[1];
    const int*   labels = (const int*)d_in[2];
    float* out = (float*)d_out;

    int total = out_size;            // B*C = 102,400,000
    int C = total / B_ROWS;          // 100000
    int n4 = total / 4;              // 25,600,000 (C % 4 == 0)

    fused_kernel<<<NBLOCKS, THREADS>>>((const float4*)logits, (float4*)out,
                                       norms, labels, C, n4);
}

// round 17
// speedup vs baseline: 1.0539x; 1.0169x over previous
#include <cuda_runtime.h>
#include <math.h>

// AdaFace logit adjustment, fused single streaming kernel with CONDITIONAL
// stats prologue.
//   out = logits * 64, except out[r, labels[r]] =
//         (cos(clip(acos(t)+g_ang, eps, pi-eps)) - g_add) * 64
// B=1024, C=100000, fp32. 800 MB HBM round trip.
//
// Grid/chunk co-design: n4 = 25,600,000 = 2048 x 12500 EXACTLY. Each block
// owns 2048 float4 (32KB) = exactly 2 trips of the 4-deep unrolled loop:
// ZERO tail iterations, so 100% of traffic keeps MLP=4 (R16 ran ~15% of its
// bytes through the MLP=1 tail loop). 12500 blocks ~= 14 waves of scheduler
// backfill (wave-granularity scaling measured monotone: 70.9/74.1/78.7/81.2%
// DRAM at 1/1.33/4/8 waves). Only ~8% of blocks contain a target row
// (decidable from labels alone); the rest skip the stats reduction (2 label
// loads + 1 barrier). Natural 40-reg codegen preserves the load batch.

#define B_ROWS   1024
#define SCALE    64.0f
#define MARGIN   0.4f
#define H_CONST  0.333f
#define EPS_CONST 1e-3f
#define THREADS  256
#define NBLOCKS  12500
#define MAXT     4

__device__ __forceinline__ float block_sum_256(float v, float* red) {
    #pragma unroll
    for (int o = 16; o > 0; o >>= 1)
        v += __shfl_down_sync(0xffffffffu, v, o);
    int lane = threadIdx.x & 31;
    int warp = threadIdx.x >> 5;
    if (lane == 0) red[warp] = v;
    __syncthreads();
    if (warp == 0) {
        v = (lane < THREADS / 32) ? red[lane] : 0.0f;
        #pragma unroll
        for (int o = 4; o > 0; o >>= 1)
            v += __shfl_down_sync(0xffffffffu, v, o);
        if (lane == 0) red[0] = v;
    }
    __syncthreads();
    float r = red[0];
    __syncthreads();
    return r;
}

__global__ void __launch_bounds__(THREADS)
fused_kernel(const float4* __restrict__ in,
             float4* __restrict__ out,
             const float* __restrict__ norms,
             const int*   __restrict__ labels,
             int C, int n4) {
    __shared__ float red[THREADS / 32];
    __shared__ int   s_ntgt;
    __shared__ int   s_tgt[MAXT];      // flat element index
    __shared__ int   s_row[MAXT];      // owning row
    __shared__ float s_ga[MAXT];
    __shared__ float s_gd[MAXT];

    const int tid = threadIdx.x;

    // ---- block-contiguous chunk: 2048 float4 = 32KB, spans <= 2 rows ----
    int chunk4 = (n4 + gridDim.x - 1) / gridDim.x;   // == 2048 exactly
    int i40 = blockIdx.x * chunk4;
    if (i40 >= n4) return;
    int i41 = min(n4, i40 + chunk4);

    // ---- cheap target test: labels only, no stats ----
    if (tid == 0) s_ntgt = 0;
    __syncthreads();
    int e0 = i40 * 4;
    int e1 = i41 * 4;                  // exclusive; fits int (<= 102.4M)
    int r0 = e0 / C;
    int r1 = (e1 - 1) / C;
    int nrows = r1 - r0 + 1;           // 1..2
    if (tid < nrows && tid < MAXT) {
        int r = r0 + tid;
        int tgt = r * C + __ldg(&labels[r]);   // < 102.4M, fits int
        if (tgt >= e0 && tgt < e1) {
            int slot = atomicAdd(&s_ntgt, 1);
            s_tgt[slot] = tgt;
            s_row[slot] = r;
        }
    }
    __syncthreads();
    const int ntgt = s_ntgt;           // block-uniform

    // ---- stats prologue: ONLY if this block owns a target (~8% of blocks) ----
    if (ntgt) {
        float xl[B_ROWS / THREADS];
        float acc = 0.0f;
        #pragma unroll
        for (int k = 0; k < B_ROWS / THREADS; k++) {
            float x = norms[tid + k * THREADS];
            x = fminf(fmaxf(x, 1e-3f), 100.0f);
            xl[k] = x;
            acc += x;
        }
        float mean = block_sum_256(acc, red) * (1.0f / B_ROWS);
        float vacc = 0.0f;
        #pragma unroll
        for (int k = 0; k < B_ROWS / THREADS; k++) {
            float d = xl[k] - mean;
            vacc += d * d;
        }
        float stdv = sqrtf(block_sum_256(vacc, red) * (1.0f / (B_ROWS - 1)));
        float inv_sh = H_CONST / (stdv + EPS_CONST);

        if (tid < ntgt) {
            int r = s_row[tid];
            float x = fminf(fmaxf(norms[r], 1e-3f), 100.0f);
            float ms = (x - mean) * inv_sh;
            ms = fminf(fmaxf(ms, -1.0f), 1.0f);
            s_ga[tid] = -MARGIN * ms;
            s_gd[tid] = MARGIN + MARGIN * ms;
        }
        __syncthreads();
    }

    // ---- stream the chunk (exactly 2 full unrolled trips, no tail) ----
    auto patch = [&](float4& v, int i4) {
        for (int t = 0; t < ntgt; t++) {
            int tg = s_tgt[t];
            if (i4 == (tg >> 2)) {
                int c = tg & 3;
                float tv = (c == 0) ? v.x : (c == 1) ? v.y : (c == 2) ? v.z : v.w;
                float theta = acosf(tv) + s_ga[t];
                theta = fminf(fmaxf(theta, EPS_CONST), (float)M_PI - EPS_CONST);
                float nt = cosf(theta) - s_gd[t];
                switch (c) {
                    case 0: v.x = nt; break;
                    case 1: v.y = nt; break;
                    case 2: v.z = nt; break;
                    default: v.w = nt; break;
                }
            }
        }
    };

    int i = i40 + tid;
    for (; i + 3 * THREADS < i41; i += 4 * THREADS) {
        float4 v0 = __ldcs(&in[i]);
        float4 v1 = __ldcs(&in[i + THREADS]);
        float4 v2 = __ldcs(&in[i + 2 * THREADS]);
        float4 v3 = __ldcs(&in[i + 3 * THREADS]);
        if (ntgt) {
            patch(v0, i);
            patch(v1, i + THREADS);
            patch(v2, i + 2 * THREADS);
            patch(v3, i + 3 * THREADS);
        }
        v0.x *= SCALE; v0.y *= SCALE; v0.z *= SCALE; v0.w *= SCALE;
        v1.x *= SCALE; v1.y *= SCALE; v1.z *= SCALE; v1.w *= SCALE;
        v2.x *= SCALE; v2.y *= SCALE; v2.z *= SCALE; v2.w *= SCALE;
        v3.x *= SCALE; v3.y *= SCALE; v3.z *= SCALE; v3.w *= SCALE;
        __stcs(&out[i],               v0);
        __stcs(&out[i + THREADS],     v1);
        __stcs(&out[i + 2 * THREADS], v2);
        __stcs(&out[i + 3 * THREADS], v3);
    }
    // Tail (never executes for NBLOCKS=12500; kept for safety w/ other shapes)
    for (; i < i41; i += THREADS) {
        float4 v = __ldcs(&in[i]);
        if (ntgt) patch(v, i);
        v.x *= SCALE; v.y *= SCALE; v.z *= SCALE; v.w *= SCALE;
        __stcs(&out[i], v);
    }
}

extern "C" void kernel_launch(void* const* d_in, const int* in_sizes, int n_in,
                              void* d_out, int out_size) {
    const float* logits = (const float*)d_in[0];
    const float* norms  = (const float*)d_in[1];
    const int*   labels = (const int*)d_in[2];
    float* out = (float*)d_out;

    int total = out_size;            // B*C = 102,400,000
    int C = total / B_ROWS;          // 100000
    int n4 = total / 4;              // 25,600,000 = 2048 * 12500 exactly

    fused_kernel<<<NBLOCKS, THREADS>>>((const float4*)logits, (float4*)out,
                                       norms, labels, C, n4);
}